// round 1
// baseline (speedup 1.0000x reference)
#include <cuda_runtime.h>
#include <math.h>
#include <stdint.h>

#define NN   25000
#define NE   500000
#define NDIM 32
#define EDIM 19
#define GG   200
#define KIN  51   // NDIM + EDIM

// ---------------- scratch (device globals: no runtime allocation) ----------
static __device__ float    g_hv[NN * GG];                 // hv_new            20 MB
static __device__ float    g_he1T[(size_t)GG * NE];       // he1 transposed   400 MB
static __device__ float    g_logits[NE];                  //                    2 MB
static __device__ float    g_ex[NE];                      //                    2 MB
static __device__ unsigned g_menc[NN];                    // encoded seg-max
static __device__ float    g_denom[NN];
static __device__ float    g_asum[NN];
static __device__ float    g_s[NN * GG];                  // sum a*he1         20 MB
static __device__ float    g_ctx[NN * GG];                // elu context       20 MB

// ---------------- helpers ---------------------------------------------------
__device__ __forceinline__ float lrelu(float x) { return x > 0.f ? x : 0.01f * x; }

// order-preserving float->uint encoding for atomicMax
__device__ __forceinline__ unsigned encf(float f) {
    unsigned u = __float_as_uint(f);
    return (u & 0x80000000u) ? ~u : (u | 0x80000000u);
}
__device__ __forceinline__ float decf(unsigned u) {
    return __uint_as_float((u & 0x80000000u) ? (u & 0x7fffffffu) : ~u);
}

// ---------------- k_init ----------------------------------------------------
__global__ void k_init() {
    int idx = blockIdx.x * blockDim.x + threadIdx.x;
    if (idx < NN * GG) g_s[idx] = 0.f;
    if (idx < NN) { g_denom[idx] = 0.f; g_asum[idx] = 0.f; g_menc[idx] = 0u; }
}

// ---------------- k_nodeproj: hv_new = lrelu(nf @ Wn^T + bn) ----------------
// 256 threads, 32 nodes/block; warp lanes = nodes, warp = 25-output group.
__global__ void k_nodeproj(const float* __restrict__ nf,
                           const float* __restrict__ Wn,
                           const float* __restrict__ bn) {
    __shared__ float sm[7656];              // [0,6400) W | [6400,6600) b | [6600,7656) in
    float* w_s = sm;
    float* b_s = sm + 6400;
    float* in_s = sm + 6600;                // 32 x 33 (pad)
    float* out_s = sm;                      // reused after compute: 32 x 201 -> need 6432 <= 6600+? (fits [0,6432))
    int tid = threadIdx.x;
    int n0 = blockIdx.x * 32;

    for (int i = tid; i < GG * NDIM; i += 256) w_s[i] = Wn[i];
    for (int i = tid; i < GG; i += 256) b_s[i] = bn[i];
    for (int i = tid; i < 32 * NDIM; i += 256) {
        int n = i >> 5, k = i & 31;
        float v = 0.f;
        if (n0 + n < NN) v = nf[(n0 + n) * NDIM + k];
        in_s[n * 33 + k] = v;
    }
    __syncthreads();

    int nl = tid & 31, grp = tid >> 5;      // grp 0..7 -> 25 outputs each
    float acc[25];
#pragma unroll
    for (int o = 0; o < 25; o++) acc[o] = b_s[grp * 25 + o];
    for (int k = 0; k < NDIM; k++) {
        float iv = in_s[nl * 33 + k];
#pragma unroll
        for (int o = 0; o < 25; o++) acc[o] += iv * w_s[(grp * 25 + o) * NDIM + k];
    }
    __syncthreads();                        // w_s no longer needed
#pragma unroll
    for (int o = 0; o < 25; o++) {
        float v = acc[o];
        out_s[nl * 201 + grp * 25 + o] = lrelu(v);
    }
    __syncthreads();
    for (int i = tid; i < 32 * GG; i += 256) {
        int n = i / GG, o = i - n * GG;
        if (n0 + n < NN) g_hv[(n0 + n) * GG + o] = out_s[n * 201 + o];
    }
}

// ---------------- k_edge1: he1 (transposed store) + fused logits ------------
// 256 threads, 64 edges/block. grp = tid>>6 (0..3) handles 50 outputs.
// smem floats: W1 10200 | W2 400 | b1 200 | in 64*53 | part 256 | src 64 | dst 64
#define E1_W1   0
#define E1_W2   10200
#define E1_B1   10600
#define E1_IN   10800
#define E1_PART 14192
#define E1_SRC  14448
#define E1_DST  14512
#define E1_SMEM_FLOATS 14576

__global__ void k_edge1(const float* __restrict__ nf,
                        const float* __restrict__ ef,
                        const int* __restrict__ src,
                        const int* __restrict__ dst,
                        const float* __restrict__ We1,
                        const float* __restrict__ be1,
                        const float* __restrict__ We2,
                        const float* __restrict__ be2) {
    extern __shared__ float sm[];
    float* w1 = sm + E1_W1;
    float* w2 = sm + E1_W2;
    float* b1 = sm + E1_B1;
    float* in_s = sm + E1_IN;               // 64 x 53
    float* part = sm + E1_PART;             // 4 x 64
    int* src_s = (int*)(sm + E1_SRC);
    int* dst_s = (int*)(sm + E1_DST);

    int tid = threadIdx.x;
    int e0 = blockIdx.x * 64;
    int EV = NE - e0; if (EV > 64) EV = 64;

    if (tid < 64) {
        int v = (tid < EV) ? src[e0 + tid] : 0;
        src_s[tid] = v;
        int d = (tid < EV) ? dst[e0 + tid] : 0;
        dst_s[tid] = d;
    }
    for (int i = tid; i < GG * KIN; i += 256) w1[i] = We1[i];
    for (int i = tid; i < 2 * GG; i += 256) w2[i] = We2[i];
    for (int i = tid; i < GG; i += 256) b1[i] = be1[i];
    __syncthreads();                        // src_s ready for the gather below
    for (int i = tid; i < 64 * KIN; i += 256) {
        int e = i / KIN, k = i - e * KIN;
        float v = 0.f;
        if (e < EV) {
            v = (k < NDIM) ? nf[src_s[e] * NDIM + k]
                           : ef[(e0 + e) * EDIM + (k - NDIM)];
        }
        in_s[e * 53 + k] = v;
    }
    __syncthreads();

    int el = tid & 63, grp = tid >> 6;      // warp-uniform grp
    float acc[50];
#pragma unroll
    for (int o = 0; o < 50; o++) acc[o] = b1[grp * 50 + o];
    for (int k = 0; k < KIN; k++) {
        float iv = in_s[el * 53 + k];
#pragma unroll
        for (int o = 0; o < 50; o++) acc[o] += iv * w1[(grp * 50 + o) * KIN + k];
    }

    bool valid = (el < EV);
    int eg = e0 + el;
    int d = dst_s[el];
    float dot = 0.f;
#pragma unroll
    for (int o = 0; o < 50; o++) {
        float v = lrelu(acc[o]);
        if (valid) g_he1T[(size_t)(grp * 50 + o) * NE + eg] = v;
        dot += v * w2[GG + grp * 50 + o];
    }
    // hv_new[dst] part of the logit dot (50 entries per group)
    const float* hvrow = g_hv + (size_t)d * GG + grp * 50;
#pragma unroll 10
    for (int o = 0; o < 50; o++) dot += hvrow[o] * w2[grp * 50 + o];
    part[grp * 64 + el] = dot;
    __syncthreads();

    if (tid < 64 && tid < EV) {
        float l = part[tid] + part[64 + tid] + part[128 + tid] + part[192 + tid] + be2[0];
        l = lrelu(l);
        g_logits[e0 + tid] = l;
        atomicMax(&g_menc[dst_s[tid]], encf(l));
    }
}

// ---------------- k_exp: ex = exp(logit - m[dst]); denom += ex --------------
__global__ void k_exp(const int* __restrict__ dst) {
    int idx = blockIdx.x * blockDim.x + threadIdx.x;
    if (idx >= NE) return;
    int d = dst[idx];
    float m = decf(g_menc[d]);
    float ex = __expf(g_logits[idx] - m);
    g_ex[idx] = ex;
    atomicAdd(&g_denom[d], ex);
}

// ---------------- k_scatter: s[dst] += a * he1; asum[dst] += a --------------
__global__ void k_scatter(const int* __restrict__ dst) {
    int idx = blockIdx.x * blockDim.x + threadIdx.x;
    if (idx >= NE) return;
    int d = dst[idx];
    float a = g_ex[idx] / g_denom[d];
    atomicAdd(&g_asum[d], a);
    const float* hcol = g_he1T + idx;
    float* srow = g_s + (size_t)d * GG;
#pragma unroll 5
    for (int o = 0; o < GG; o += 4) {
        float v0 = a * hcol[(size_t)(o + 0) * NE];
        float v1 = a * hcol[(size_t)(o + 1) * NE];
        float v2 = a * hcol[(size_t)(o + 2) * NE];
        float v3 = a * hcol[(size_t)(o + 3) * NE];
        asm volatile("red.global.add.v4.f32 [%0], {%1, %2, %3, %4};"
                     :: "l"(srow + o), "f"(v0), "f"(v1), "f"(v2), "f"(v3)
                     : "memory");
    }
}

// ---------------- k_ctx: context = elu(s @ Wet^T + asum * bet) --------------
// 256 threads, 32 nodes/block, K chunked by 50 through smem.
#define CX_IN  0            // 32 x 201
#define CX_W   6432         // 200 x 50
#define CX_B   16432        // 200
#define CX_AS  16632        // 32
#define CX_SMEM_FLOATS 16664

__global__ void k_ctx(const float* __restrict__ Wet, const float* __restrict__ bet) {
    extern __shared__ float sm[];
    float* in_s = sm + CX_IN;
    float* w_s  = sm + CX_W;
    float* b_s  = sm + CX_B;
    float* as_s = sm + CX_AS;
    float* out_s = sm + CX_W;               // reuse after compute (needs 6432 <= 10000)

    int tid = threadIdx.x;
    int n0 = blockIdx.x * 32;

    for (int i = tid; i < 32 * GG; i += 256) {
        int n = i / GG, k = i - n * GG;
        in_s[n * 201 + k] = (n0 + n < NN) ? g_s[(n0 + n) * GG + k] : 0.f;
    }
    for (int i = tid; i < GG; i += 256) b_s[i] = bet[i];
    if (tid < 32) as_s[tid] = (n0 + tid < NN) ? g_asum[n0 + tid] : 0.f;

    int nl = tid & 31, grp = tid >> 5;      // grp 0..7 -> 25 outputs
    float acc[25];
#pragma unroll
    for (int o = 0; o < 25; o++) acc[o] = 0.f;

    for (int kc = 0; kc < GG; kc += 50) {
        __syncthreads();
        for (int i = tid; i < GG * 50; i += 256) {
            int o = i / 50, kk = i - o * 50;
            w_s[i] = Wet[o * GG + kc + kk];
        }
        __syncthreads();
        for (int kk = 0; kk < 50; kk++) {
            float iv = in_s[nl * 201 + kc + kk];
#pragma unroll
            for (int o = 0; o < 25; o++) acc[o] += iv * w_s[(grp * 25 + o) * 50 + kk];
        }
    }
    __syncthreads();
    float as = as_s[nl];
#pragma unroll
    for (int o = 0; o < 25; o++) {
        float v = acc[o] + as * b_s[grp * 25 + o];
        out_s[nl * 201 + grp * 25 + o] = (v > 0.f) ? v : expm1f(v);
    }
    __syncthreads();
    for (int i = tid; i < 32 * GG; i += 256) {
        int n = i / GG, o = i - n * GG;
        if (n0 + n < NN) g_ctx[(n0 + n) * GG + o] = out_s[n * 201 + o];
    }
}

// ---------------- k_gru: full GRUCell + relu --------------------------------
// 256 threads, 16 nodes/block. Phase A: 1200 gate pre-activations per node
// (gi: W_ih @ ctx, gh: W_hh @ hv), weights streamed through smem in 25-k chunks.
#define GR_CTX 0            // 16 x 201
#define GR_HV  3216         // 16 x 201
#define GR_GB  6432         // 16 x 1201
#define GR_W   25648        // 400 x 25
#define GR_B   35648        // 1200
#define GR_SMEM_FLOATS 36848

__global__ void k_gru(const float* __restrict__ Wih, const float* __restrict__ bih,
                      const float* __restrict__ Whh, const float* __restrict__ bhh,
                      float* __restrict__ out) {
    extern __shared__ float sm[];
    float* ctx_s = sm + GR_CTX;
    float* hv_s  = sm + GR_HV;
    float* gb    = sm + GR_GB;
    float* w_s   = sm + GR_W;
    float* b_s   = sm + GR_B;

    int tid = threadIdx.x;
    int n0 = blockIdx.x * 16;

    for (int i = tid; i < 16 * GG; i += 256) {
        int n = i / GG, k = i - n * GG;
        bool ok = (n0 + n < NN);
        ctx_s[n * 201 + k] = ok ? g_ctx[(n0 + n) * GG + k] : 0.f;
        hv_s[n * 201 + k]  = ok ? g_hv[(n0 + n) * GG + k] : 0.f;
    }
    for (int i = tid; i < 600; i += 256) { b_s[i] = bih[i]; b_s[600 + i] = bhh[i]; }
    __syncthreads();

    int nl = tid & 15, grp = tid >> 4;      // grp 0..15, 75 rows each
    const float* inrow = (grp < 8 ? ctx_s : hv_s) + nl * 201;

    for (int ch = 0; ch < 3; ch++) {
        float acc[25];
        int Rbase = grp * 75 + ch * 25;
#pragma unroll
        for (int o = 0; o < 25; o++) acc[o] = b_s[Rbase + o];

        for (int kc = 0; kc < GG; kc += 25) {
            __syncthreads();
            for (int i = tid; i < 400 * 25; i += 256) {
                int rr = i / 25, kk = i - rr * 25;
                int grp_r = rr / 25, o_r = rr - grp_r * 25;
                int R = grp_r * 75 + ch * 25 + o_r;
                const float* Wsrc = (R < 600) ? (Wih + (size_t)R * GG + kc)
                                              : (Whh + (size_t)(R - 600) * GG + kc);
                w_s[i] = Wsrc[kk];
            }
            __syncthreads();
            for (int kk = 0; kk < 25; kk++) {
                float iv = inrow[kc + kk];
#pragma unroll
                for (int o = 0; o < 25; o++) acc[o] += iv * w_s[(grp * 25 + o) * 25 + kk];
            }
        }
#pragma unroll
        for (int o = 0; o < 25; o++) gb[nl * 1201 + Rbase + o] = acc[o];
    }
    __syncthreads();

    // Phase B: gating
    for (int i = tid; i < 16 * GG; i += 256) {
        int n = i / GG, j = i - n * GG;
        if (n0 + n >= NN) continue;
        float ir = gb[n * 1201 + j];
        float iz = gb[n * 1201 + 200 + j];
        float in_ = gb[n * 1201 + 400 + j];
        float hr = gb[n * 1201 + 600 + j];
        float hz = gb[n * 1201 + 800 + j];
        float hn = gb[n * 1201 + 1000 + j];
        float r = 1.f / (1.f + __expf(-(ir + hr)));
        float z = 1.f / (1.f + __expf(-(iz + hz)));
        float nn_ = tanhf(in_ + r * hn);
        float hv = hv_s[n * 201 + j];
        float h = (1.f - z) * nn_ + z * hv;
        out[(size_t)(n0 + n) * GG + j] = fmaxf(h, 0.f);
    }
}

// ---------------- launch -----------------------------------------------------
extern "C" void kernel_launch(void* const* d_in, const int* in_sizes, int n_in,
                              void* d_out, int out_size) {
    const float* nf  = (const float*)d_in[0];
    const float* ef  = (const float*)d_in[1];
    const int*   src = (const int*)d_in[2];
    const int*   dst = (const int*)d_in[3];
    const float* Wn  = (const float*)d_in[4];
    const float* bn  = (const float*)d_in[5];
    const float* We1 = (const float*)d_in[6];
    const float* be1 = (const float*)d_in[7];
    const float* We2 = (const float*)d_in[8];
    const float* be2 = (const float*)d_in[9];
    const float* Wet = (const float*)d_in[10];
    const float* bet = (const float*)d_in[11];
    const float* Wih = (const float*)d_in[12];
    const float* bih = (const float*)d_in[13];
    const float* Whh = (const float*)d_in[14];
    const float* bhh = (const float*)d_in[15];
    float* out = (float*)d_out;

    static bool attr_done = false;
    if (!attr_done) {
        cudaFuncSetAttribute(k_edge1, cudaFuncAttributeMaxDynamicSharedMemorySize,
                             E1_SMEM_FLOATS * 4);
        cudaFuncSetAttribute(k_ctx, cudaFuncAttributeMaxDynamicSharedMemorySize,
                             CX_SMEM_FLOATS * 4);
        cudaFuncSetAttribute(k_gru, cudaFuncAttributeMaxDynamicSharedMemorySize,
                             GR_SMEM_FLOATS * 4);
        attr_done = true;
    }

    k_init<<<(NN * GG + 255) / 256, 256>>>();
    k_nodeproj<<<(NN + 31) / 32, 256>>>(nf, Wn, bn);
    k_edge1<<<(NE + 63) / 64, 256, E1_SMEM_FLOATS * 4>>>(nf, ef, src, dst,
                                                         We1, be1, We2, be2);
    k_exp<<<(NE + 255) / 256, 256>>>(dst);
    k_scatter<<<(NE + 255) / 256, 256>>>(dst);
    k_ctx<<<(NN + 31) / 32, 256, CX_SMEM_FLOATS * 4>>>(Wet, bet);
    k_gru<<<(NN + 15) / 16, 256, GR_SMEM_FLOATS * 4>>>(Wih, bih, Whh, bhh, out);
}

// round 2
// speedup vs baseline: 2.5776x; 2.5776x over previous
#include <cuda_runtime.h>
#include <math.h>
#include <stdint.h>

#define NN   25000
#define NE   500000
#define NDIM 32
#define EDIM 19
#define GG   200
#define KIN  51   // NDIM + EDIM

// ---------------- scratch (device globals) ----------------------------------
static __device__ float    g_hv[NN * GG];
static __device__ float    g_q[NN];                        // hv_new . We2[0:200]
static __device__ float    g_he1T[(size_t)GG * NE];        // he1 transposed (400 MB)
static __device__ float    g_logits[NE];
static __device__ float    g_ex[NE];
static __device__ unsigned g_menc[NN];
static __device__ float    g_denom[NN];
static __device__ float    g_asum[NN];
static __device__ float    g_s[NN * GG];
static __device__ float    g_ctx[NN * GG];
static __device__ float    g_gates[(size_t)6 * NN * GG];   // ir iz in hr hz hn (120 MB)

// ---------------- helpers ----------------------------------------------------
__device__ __forceinline__ float lrelu(float x) { return x > 0.f ? x : 0.01f * x; }

__device__ __forceinline__ unsigned encf(float f) {
    unsigned u = __float_as_uint(f);
    return (u & 0x80000000u) ? ~u : (u | 0x80000000u);
}
__device__ __forceinline__ float decf(unsigned u) {
    return __uint_as_float((u & 0x80000000u) ? (u & 0x7fffffffu) : ~u);
}

// ---------------- k_init -----------------------------------------------------
__global__ void k_init() {
    int idx = blockIdx.x * blockDim.x + threadIdx.x;
    if (idx < NN * GG) g_s[idx] = 0.f;
    if (idx < NN) { g_denom[idx] = 0.f; g_asum[idx] = 0.f; g_menc[idx] = 0u; }
}

// ---------------- k_nodeproj: hv_new = lrelu(nf @ Wn^T + bn);  q = hv.w2a ----
__global__ void k_nodeproj(const float* __restrict__ nf,
                           const float* __restrict__ Wn,
                           const float* __restrict__ bn,
                           const float* __restrict__ We2) {
    __shared__ float sm[8112];
    float* w_s  = sm;          // [0,6400)
    float* b_s  = sm + 6400;   // [6400,6600)
    float* in_s = sm + 6600;   // [6600,7656)  32 x 33
    float* w2a  = sm + 7656;   // [7656,7856)
    float* qp   = sm + 7856;   // [7856,8112)  8 x 32
    float* out_s = sm;         // reuse [0,6432)
    int tid = threadIdx.x;
    int n0 = blockIdx.x * 32;

    for (int i = tid; i < GG * NDIM; i += 256) w_s[i] = Wn[i];
    for (int i = tid; i < GG; i += 256) { b_s[i] = bn[i]; w2a[i] = We2[i]; }
    for (int i = tid; i < 32 * NDIM; i += 256) {
        int n = i >> 5, k = i & 31;
        float v = 0.f;
        if (n0 + n < NN) v = nf[(n0 + n) * NDIM + k];
        in_s[n * 33 + k] = v;
    }
    __syncthreads();

    int nl = tid & 31, grp = tid >> 5;      // 8 grps x 25 outputs
    float acc[25];
#pragma unroll
    for (int o = 0; o < 25; o++) acc[o] = b_s[grp * 25 + o];
    for (int k = 0; k < NDIM; k++) {
        float iv = in_s[nl * 33 + k];
#pragma unroll
        for (int o = 0; o < 25; o++) acc[o] += iv * w_s[(grp * 25 + o) * NDIM + k];
    }
    __syncthreads();
    float qdot = 0.f;
#pragma unroll
    for (int o = 0; o < 25; o++) {
        float v = lrelu(acc[o]);
        out_s[nl * 201 + grp * 25 + o] = v;
        qdot += v * w2a[grp * 25 + o];
    }
    qp[grp * 32 + nl] = qdot;
    __syncthreads();
    for (int i = tid; i < 32 * GG; i += 256) {
        int n = i / GG, o = i - n * GG;
        if (n0 + n < NN) g_hv[(n0 + n) * GG + o] = out_s[n * 201 + o];
    }
    if (tid < 32 && n0 + tid < NN) {
        float q = 0.f;
#pragma unroll
        for (int g = 0; g < 8; g++) q += qp[g * 32 + tid];
        g_q[n0 + tid] = q;
    }
}

// ---------------- k_edge1: he1 (transposed) + fused logits ------------------
// 256 threads. Weights loaded ONCE per block (transposed, float4-aligned),
// grid-stride over 32-edge tiles. Warp = (o-group of 25, 32 edge-lanes).
#define E1_W    0                       // 51 x 228
#define E1_B    11628                   // 200
#define E1_W2B  11828                   // 200
#define E1_IN   12032                   // 51 x 33 = 1683
#define E1_PART 13728                   // 8 x 32
#define E1_SD   13984                   // src 32 + dst 32 (ints)
#define E1_SMEM_FLOATS 14048
#define E1_NT   ((NE + 31) / 32)

__global__ void k_edge1(const float* __restrict__ nf,
                        const float* __restrict__ ef,
                        const int* __restrict__ src,
                        const int* __restrict__ dst,
                        const float* __restrict__ We1,
                        const float* __restrict__ be1,
                        const float* __restrict__ We2,
                        const float* __restrict__ be2) {
    extern __shared__ float sm[];
    float* w1   = sm + E1_W;
    float* b1   = sm + E1_B;
    float* w2b  = sm + E1_W2B;
    float* in_s = sm + E1_IN;
    float* part = sm + E1_PART;
    int* src_s  = (int*)(sm + E1_SD);
    int* dst_s  = src_s + 32;

    int tid = threadIdx.x;
    int lane = tid & 31;
    int grp = tid >> 5;                 // 0..7 -> outputs grp*25..grp*25+24

    // coalesced weight load, transposed layout w1[k*228 + grp*28 + j]
    for (int i = tid; i < GG * KIN; i += 256) {
        int r = i / KIN, k = i - r * KIN;
        int g = r / 25, j = r - g * 25;
        w1[k * 228 + g * 28 + j] = We1[i];
    }
    for (int i = tid; i < GG; i += 256) { b1[i] = be1[i]; w2b[i] = We2[GG + i]; }
    float be2v = be2[0];
    __syncthreads();

    for (int t = blockIdx.x; t < E1_NT; t += gridDim.x) {
        int e0 = t * 32;
        int EV = NE - e0; if (EV > 32) EV = 32;

        if (tid < 32) {
            src_s[tid] = (tid < EV) ? src[e0 + tid] : 0;
            dst_s[tid] = (tid < EV) ? dst[e0 + tid] : 0;
        }
        __syncthreads();

        // gather inputs: warp g loads edges g*4..g*4+3, lanes over feature dim
#pragma unroll
        for (int i = 0; i < 4; i++) {
            int ee = grp * 4 + i;
            float vn = 0.f, ve = 0.f;
            if (ee < EV) {
                int s = src_s[ee];
                vn = nf[(size_t)s * NDIM + lane];
                if (lane < EDIM) ve = ef[(size_t)(e0 + ee) * EDIM + lane];
            }
            in_s[lane * 33 + ee] = vn;
            if (lane < EDIM) in_s[(NDIM + lane) * 33 + ee] = ve;
        }
        __syncthreads();

        float acc[28];
#pragma unroll
        for (int j = 0; j < 28; j++) acc[j] = (j < 25) ? b1[grp * 25 + j] : 0.f;

        for (int k = 0; k < KIN; k++) {
            float x = in_s[k * 33 + lane];
            const float4* wp = (const float4*)&w1[k * 228 + grp * 28];
#pragma unroll
            for (int j4 = 0; j4 < 7; j4++) {
                float4 w = wp[j4];
                acc[j4 * 4 + 0] += x * w.x;
                acc[j4 * 4 + 1] += x * w.y;
                acc[j4 * 4 + 2] += x * w.z;
                acc[j4 * 4 + 3] += x * w.w;
            }
        }

        bool valid = (lane < EV);
        int eg = e0 + lane;
        float dotv = 0.f;
#pragma unroll
        for (int j = 0; j < 25; j++) {
            float v = lrelu(acc[j]);
            if (valid) g_he1T[(size_t)(grp * 25 + j) * NE + eg] = v;
            dotv += v * w2b[grp * 25 + j];
        }
        part[grp * 32 + lane] = dotv;
        __syncthreads();

        if (tid < 32 && tid < EV) {
            float l = be2v + g_q[dst_s[tid]];
#pragma unroll
            for (int g = 0; g < 8; g++) l += part[g * 32 + tid];
            l = lrelu(l);
            g_logits[e0 + tid] = l;
            atomicMax(&g_menc[dst_s[tid]], encf(l));
        }
        __syncthreads();
    }
}

// ---------------- k_exp ------------------------------------------------------
__global__ void k_exp(const int* __restrict__ dst) {
    int idx = blockIdx.x * blockDim.x + threadIdx.x;
    if (idx >= NE) return;
    int d = dst[idx];
    float m = decf(g_menc[d]);
    float ex = __expf(g_logits[idx] - m);
    g_ex[idx] = ex;
    atomicAdd(&g_denom[d], ex);
}

// ---------------- k_scatter --------------------------------------------------
__global__ void k_scatter(const int* __restrict__ dst) {
    int idx = blockIdx.x * blockDim.x + threadIdx.x;
    if (idx >= NE) return;
    int d = dst[idx];
    float a = g_ex[idx] / g_denom[d];
    atomicAdd(&g_asum[d], a);
    const float* hcol = g_he1T + idx;
    float* srow = g_s + (size_t)d * GG;
#pragma unroll 5
    for (int o = 0; o < GG; o += 4) {
        float v0 = a * hcol[(size_t)(o + 0) * NE];
        float v1 = a * hcol[(size_t)(o + 1) * NE];
        float v2 = a * hcol[(size_t)(o + 2) * NE];
        float v3 = a * hcol[(size_t)(o + 3) * NE];
        asm volatile("red.global.add.v4.f32 [%0], {%1, %2, %3, %4};"
                     :: "l"(srow + o), "f"(v0), "f"(v1), "f"(v2), "f"(v3)
                     : "memory");
    }
}

// ---------------- k_ctx: context = elu(s @ Wet^T + asum * bet) ---------------
// 32 nodes/block, K chunked by 50 through transposed smem weights.
#define CX_IN   0                       // 200 x 33 = 6600
#define CX_W    6600                    // 50 x 228 = 11400
#define CX_BET  18000                   // 200
#define CX_AS   18200                   // 32
#define CX_SMEM_FLOATS 18240

__global__ void k_ctx(const float* __restrict__ Wet, const float* __restrict__ bet) {
    extern __shared__ float sm[];
    float* in_s  = sm + CX_IN;
    float* w_s   = sm + CX_W;
    float* bet_s = sm + CX_BET;
    float* as_s  = sm + CX_AS;
    float* out_s = sm + CX_W;           // reuse after compute (32 x 201 = 6432)

    int tid = threadIdx.x;
    int n0 = blockIdx.x * 32;
    int lane = tid & 31, grp = tid >> 5;

    for (int i = tid; i < 32 * GG; i += 256) {
        int n = i / GG, k = i - n * GG;
        in_s[k * 33 + n] = (n0 + n < NN) ? g_s[(size_t)(n0 + n) * GG + k] : 0.f;
    }
    for (int i = tid; i < GG; i += 256) bet_s[i] = bet[i];
    if (tid < 32) as_s[tid] = (n0 + tid < NN) ? g_asum[n0 + tid] : 0.f;

    float acc[28];
#pragma unroll
    for (int j = 0; j < 28; j++) acc[j] = 0.f;

    for (int c = 0; c < 4; c++) {
        __syncthreads();
        for (int i = tid; i < GG * 50; i += 256) {
            int r = i / 50, kk = i - r * 50;
            int g = r / 25, j = r - g * 25;
            w_s[kk * 228 + g * 28 + j] = Wet[(size_t)r * GG + c * 50 + kk];
        }
        __syncthreads();
        for (int kk = 0; kk < 50; kk++) {
            float x = in_s[(c * 50 + kk) * 33 + lane];
            const float4* wp = (const float4*)&w_s[kk * 228 + grp * 28];
#pragma unroll
            for (int j4 = 0; j4 < 7; j4++) {
                float4 w = wp[j4];
                acc[j4 * 4 + 0] += x * w.x;
                acc[j4 * 4 + 1] += x * w.y;
                acc[j4 * 4 + 2] += x * w.z;
                acc[j4 * 4 + 3] += x * w.w;
            }
        }
    }
    __syncthreads();
    float as = as_s[lane];
#pragma unroll
    for (int j = 0; j < 25; j++) {
        float v = acc[j] + as * bet_s[grp * 25 + j];
        out_s[lane * 201 + grp * 25 + j] = (v > 0.f) ? v : expm1f(v);
    }
    __syncthreads();
    for (int i = tid; i < 32 * GG; i += 256) {
        int n = i / GG, o = i - n * GG;
        if (n0 + n < NN) g_ctx[(size_t)(n0 + n) * GG + o] = out_s[n * 201 + o];
    }
}

// ---------------- k_gru: 6 gate GEMM tiles (blockIdx.y) ----------------------
// ty 0..2: Wih rows ty*200, input ctx. ty 3..5: Whh rows (ty-3)*200, input hv.
#define GR_IN   0                       // 200 x 33
#define GR_W    6600                    // 50 x 228
#define GR_B    18000                   // 200
#define GR_SMEM_FLOATS 18200

__global__ void k_gru(const float* __restrict__ Wih, const float* __restrict__ bih,
                      const float* __restrict__ Whh, const float* __restrict__ bhh) {
    extern __shared__ float sm[];
    float* in_s = sm + GR_IN;
    float* w_s  = sm + GR_W;
    float* b_s  = sm + GR_B;
    float* out_s = sm + GR_W;           // reuse

    int tid = threadIdx.x;
    int ty = blockIdx.y;
    int n0 = blockIdx.x * 32;
    int lane = tid & 31, grp = tid >> 5;

    const float* srcmat = (ty < 3) ? g_ctx : g_hv;
    const float* W = (ty < 3) ? (Wih + (size_t)ty * GG * GG)
                              : (Whh + (size_t)(ty - 3) * GG * GG);
    const float* b = (ty < 3) ? (bih + ty * GG) : (bhh + (ty - 3) * GG);

    for (int i = tid; i < 32 * GG; i += 256) {
        int n = i / GG, k = i - n * GG;
        in_s[k * 33 + n] = (n0 + n < NN) ? srcmat[(size_t)(n0 + n) * GG + k] : 0.f;
    }
    for (int i = tid; i < GG; i += 256) b_s[i] = b[i];
    __syncthreads();

    float acc[28];
#pragma unroll
    for (int j = 0; j < 28; j++) acc[j] = (j < 25) ? b_s[grp * 25 + j] : 0.f;

    for (int c = 0; c < 4; c++) {
        __syncthreads();
        for (int i = tid; i < GG * 50; i += 256) {
            int r = i / 50, kk = i - r * 50;
            int g = r / 25, j = r - g * 25;
            w_s[kk * 228 + g * 28 + j] = W[(size_t)r * GG + c * 50 + kk];
        }
        __syncthreads();
        for (int kk = 0; kk < 50; kk++) {
            float x = in_s[(c * 50 + kk) * 33 + lane];
            const float4* wp = (const float4*)&w_s[kk * 228 + grp * 28];
#pragma unroll
            for (int j4 = 0; j4 < 7; j4++) {
                float4 w = wp[j4];
                acc[j4 * 4 + 0] += x * w.x;
                acc[j4 * 4 + 1] += x * w.y;
                acc[j4 * 4 + 2] += x * w.z;
                acc[j4 * 4 + 3] += x * w.w;
            }
        }
    }
    __syncthreads();                    // w_s -> out_s reuse
#pragma unroll
    for (int j = 0; j < 25; j++) out_s[lane * 201 + grp * 25 + j] = acc[j];
    __syncthreads();
    float* gout = g_gates + (size_t)ty * NN * GG;
    for (int i = tid; i < 32 * GG; i += 256) {
        int n = i / GG, o = i - n * GG;
        if (n0 + n < NN) gout[(size_t)(n0 + n) * GG + o] = out_s[n * 201 + o];
    }
}

// ---------------- k_gate: elementwise GRU combine + relu ---------------------
__global__ void k_gate(float* __restrict__ out) {
    int idx = blockIdx.x * blockDim.x + threadIdx.x;
    if (idx >= NN * GG) return;
    const size_t S = (size_t)NN * GG;
    float ir = g_gates[idx],         iz = g_gates[S + idx],     inn = g_gates[2 * S + idx];
    float hr = g_gates[3 * S + idx], hz = g_gates[4 * S + idx], hn  = g_gates[5 * S + idx];
    float r = 1.f / (1.f + __expf(-(ir + hr)));
    float z = 1.f / (1.f + __expf(-(iz + hz)));
    float n = tanhf(inn + r * hn);
    float hv = g_hv[idx];
    float h = (1.f - z) * n + z * hv;
    out[idx] = fmaxf(h, 0.f);
}

// ---------------- launch -----------------------------------------------------
extern "C" void kernel_launch(void* const* d_in, const int* in_sizes, int n_in,
                              void* d_out, int out_size) {
    const float* nf  = (const float*)d_in[0];
    const float* ef  = (const float*)d_in[1];
    const int*   src = (const int*)d_in[2];
    const int*   dst = (const int*)d_in[3];
    const float* Wn  = (const float*)d_in[4];
    const float* bn  = (const float*)d_in[5];
    const float* We1 = (const float*)d_in[6];
    const float* be1 = (const float*)d_in[7];
    const float* We2 = (const float*)d_in[8];
    const float* be2 = (const float*)d_in[9];
    const float* Wet = (const float*)d_in[10];
    const float* bet = (const float*)d_in[11];
    const float* Wih = (const float*)d_in[12];
    const float* bih = (const float*)d_in[13];
    const float* Whh = (const float*)d_in[14];
    const float* bhh = (const float*)d_in[15];
    float* out = (float*)d_out;

    static bool attr_done = false;
    if (!attr_done) {
        cudaFuncSetAttribute(k_edge1, cudaFuncAttributeMaxDynamicSharedMemorySize,
                             E1_SMEM_FLOATS * 4);
        cudaFuncSetAttribute(k_ctx, cudaFuncAttributeMaxDynamicSharedMemorySize,
                             CX_SMEM_FLOATS * 4);
        cudaFuncSetAttribute(k_gru, cudaFuncAttributeMaxDynamicSharedMemorySize,
                             GR_SMEM_FLOATS * 4);
        attr_done = true;
    }

    k_init<<<(NN * GG + 255) / 256, 256>>>();
    k_nodeproj<<<(NN + 31) / 32, 256>>>(nf, Wn, bn, We2);
    k_edge1<<<1184, 256, E1_SMEM_FLOATS * 4>>>(nf, ef, src, dst, We1, be1, We2, be2);
    k_exp<<<(NE + 255) / 256, 256>>>(dst);
    k_scatter<<<(NE + 255) / 256, 256>>>(dst);
    k_ctx<<<(NN + 31) / 32, 256, CX_SMEM_FLOATS * 4>>>(Wet, bet);
    dim3 gg((NN + 31) / 32, 6);
    k_gru<<<gg, 256, GR_SMEM_FLOATS * 4>>>(Wih, bih, Whh, bhh);
    k_gate<<<(NN * GG + 255) / 256, 256>>>(out);
}